// round 2
// baseline (speedup 1.0000x reference)
#include <cuda_runtime.h>
#include <cuda_fp16.h>
#include <math.h>

#define BB 2
#define CC 64
#define NPTS 4096
#define MM 256
#define NS 32
#define R2 0.04f

// -------- scratch (device globals; no allocation allowed) --------
__device__ int     g_idx[BB*NPTS*NS];
__device__ int     g_cnt[BB*NPTS];
__device__ __half2 g_featsh[BB*NPTS*(MM/2)];  // (B, N, M/2) fp16 pairs
__device__ float   g_oraw[BB*CC*NPTS];        // (B, C, N)
__device__ float   g_G[BB*CC*CC];             // per-batch Gram of x
__device__ float   g_sv[BB*CC];               // per-batch row sums of x
__device__ double  g_s1[8], g_ss1[8], g_s2[8], g_ss2[8], g_s3[8], g_ss3[8];

__device__ __forceinline__ float gelu_f(float v) {
    return 0.5f * v * (1.0f + erff(v * 0.70710678118654752f));
}

// -------- K0: zero scratch --------
__global__ void k_zero() {
    int i = blockIdx.x * 256 + threadIdx.x;
    if (i < BB*NPTS) { g_cnt[i] = 0; }
    if (i < BB*CC*CC) { g_G[i] = 0.f; }
    if (i < BB*CC) { g_sv[i] = 0.f; }
    if (i < 8) {
        g_s1[i]=0.0; g_ss1[i]=0.0;
        g_s2[i]=0.0; g_ss2[i]=0.0;
        g_s3[i]=0.0; g_ss3[i]=0.0;
    }
}

// -------- K1: ball query (one warp per query point) + counts --------
__global__ void k_ball(const float* __restrict__ pos) {
    extern __shared__ float sm[];
    float* sx = sm;
    float* sy = sm + NPTS;
    float* sz = sm + 2*NPTS;
    int*   widx = (int*)(sm + 3*NPTS);   // 16 warps * 32 entries

    int tid = threadIdx.x;
    int b = blockIdx.x / (NPTS/16);
    int nbase = (blockIdx.x % (NPTS/16)) * 16;
    const float* pb = pos + b * 3 * NPTS;
    for (int i = tid; i < NPTS; i += 512) {
        sx[i] = pb[i];
        sy[i] = pb[NPTS + i];
        sz[i] = pb[2*NPTS + i];
    }
    __syncthreads();

    int warp = tid >> 5, lane = tid & 31;
    int n = nbase + warp;
    float xn = sx[n], yn = sy[n], zn = sz[n];
    float sqn = xn*xn + yn*yn + zn*zn;
    int cnt = 0, firstm = -1;
    int* wl = widx + warp * NS;

    for (int base = 0; base < NPTS && cnt < NS; base += 32) {
        int mq = base + lane;
        float xm = sx[mq], ym = sy[mq], zm = sz[mq];
        float sqm = xm*xm + ym*ym + zm*zm;
        float dot = xn*xm + yn*ym + zn*zm;
        float d = sqn + sqm - 2.0f * dot;
        bool q = !(d > R2);
        unsigned mask = __ballot_sync(0xffffffffu, q);
        if (mask) {
            if (firstm < 0) firstm = base + __ffs(mask) - 1;
            int nq = __popc(mask);
            int slots = NS - cnt;
            if (q) {
                int rank = __popc(mask & ((1u << lane) - 1u));
                if (rank < slots) wl[cnt + rank] = mq;
            }
            cnt += (nq < slots) ? nq : slots;
        }
    }
    __syncwarp();
    if (lane >= cnt) wl[lane] = firstm;   // pad with first qualifying index
    __syncwarp();
    int j = wl[lane];
    g_idx[(b*NPTS + n)*NS + lane] = j;
    atomicAdd(&g_cnt[b*NPTS + j], 1);
}

// -------- K2a: Gram matrix G = x x^T + row sums, per batch --------
// grid (16 n-chunks, B), block 256, dyn smem 64*257 floats
__global__ void k_gram(const float* __restrict__ x) {
    extern __shared__ float sx[];          // 64 x 257 pitch
    int b = blockIdx.y, n0 = blockIdx.x * 256;
    int tid = threadIdx.x;
    for (int e = tid; e < CC*256; e += 256) {
        int c = e >> 8, nn = e & 255;
        sx[c*257 + nn] = x[(b*CC + c)*NPTS + n0 + nn];
    }
    __syncthreads();

    // 4096 pairs / 256 threads = 16 pairs each
#pragma unroll
    for (int i = 0; i < 16; i++) {
        int p = tid * 16 + i;
        int c = p >> 6, c2 = p & 63;
        const float* r1 = sx + c*257;
        const float* r2 = sx + c2*257;
        float acc = 0.f;
#pragma unroll 8
        for (int nn = 0; nn < 256; nn++) acc = fmaf(r1[nn], r2[nn], acc);
        atomicAdd(&g_G[b*CC*CC + p], acc);
    }
    if (tid < CC) {
        const float* r = sx + tid*257;
        float s = 0.f;
#pragma unroll 8
        for (int nn = 0; nn < 256; nn++) s += r[nn];
        atomicAdd(&g_sv[b*CC + tid], s);
    }
}

// -------- K2b: GN1 group stats from Gram --------
// grid 64 (b = blk>>5, m0 = (blk&31)*8), block 256 = 8 m x 32 lanes
__global__ void k_stats1(const float* __restrict__ w1, const float* __restrict__ b1) {
    __shared__ float sG[CC*CC];     // 16KB
    __shared__ float sw[8][CC];
    __shared__ float ssv[CC];
    int b = blockIdx.x >> 5;
    int m0 = (blockIdx.x & 31) * 8;
    int tid = threadIdx.x;
    for (int e = tid; e < CC*CC; e += 256) sG[e] = g_G[b*CC*CC + e];
    for (int e = tid; e < 8*CC; e += 256) sw[e >> 6][e & 63] = w1[(m0 + (e >> 6))*CC + (e & 63)];
    if (tid < CC) ssv[tid] = g_sv[b*CC + tid];
    __syncthreads();

    int mi = tid >> 5, lane = tid & 31;
    float q = 0.f, l = 0.f;
    for (int c = 0; c < CC; c++) {
        float wc = sw[mi][c];
        float inner = 0.f;
#pragma unroll
        for (int c2 = lane; c2 < CC; c2 += 32)
            inner = fmaf(sw[mi][c2], sG[c*CC + c2], inner);
        q = fmaf(wc, inner, q);
    }
#pragma unroll
    for (int c = lane; c < CC; c += 32) l = fmaf(sw[mi][c], ssv[c], l);
#pragma unroll
    for (int o = 16; o > 0; o >>= 1) {
        q += __shfl_down_sync(0xffffffffu, q, o);
        l += __shfl_down_sync(0xffffffffu, l, o);
    }
    if (lane == 0) {
        int m = m0 + mi;
        float bb = b1[m];
        double sum_h = (double)l + 4096.0 * (double)bb;
        double ss_h  = (double)q + 2.0 * (double)bb * (double)l + 4096.0 * (double)bb * (double)bb;
        int bg = b*4 + (m0 >> 6);
        atomicAdd(&g_s1[bg],  sum_h);
        atomicAdd(&g_ss1[bg], ss_h);
    }
}

// -------- K3: h = w1@x + b1, GN1 + GELU applied in epilogue,
//          write feats fp16 transposed, fused count-weighted GN2 stats --------
// grid (N/64, M/64, B), block 256, thread 4x4 micro-tile
__global__ void k_gemm1f(const float* __restrict__ x, const float* __restrict__ w1,
                         const float* __restrict__ b1, const float* __restrict__ g1,
                         const float* __restrict__ be1, const float* __restrict__ wd) {
    __shared__ float sW[64][65];
    __shared__ float sX[64][64];
    __shared__ float sT[64][65];     // transpose staging: [n_local][m_local]
    __shared__ float red1[256], red2[256];
    int b = blockIdx.z, m0 = blockIdx.y * 64, n0 = blockIdx.x * 64;
    int tid = threadIdx.x;
    int bg = b*4 + blockIdx.y;       // 64-m tile == one group

    for (int e = tid; e < 4096; e += 256) {
        int mr = e >> 6, cr = e & 63;
        sW[mr][cr] = w1[(m0 + mr)*CC + cr];
    }
    for (int e = tid; e < 4096; e += 256) {
        int cr = e >> 6, nr = e & 63;
        sX[cr][nr] = x[(b*CC + cr)*NPTS + n0 + nr];
    }
    __syncthreads();

    int tx = tid & 15, ty = tid >> 4;
    float acc[4][4] = {};
#pragma unroll 16
    for (int k = 0; k < 64; k++) {
        float a[4], h[4];
#pragma unroll
        for (int i = 0; i < 4; i++) a[i] = sW[ty*4 + i][k];
#pragma unroll
        for (int j = 0; j < 4; j++) h[j] = sX[k][tx*4 + j];
#pragma unroll
        for (int i = 0; i < 4; i++)
#pragma unroll
            for (int j = 0; j < 4; j++)
                acc[i][j] = fmaf(a[i], h[j], acc[i][j]);
    }

    // GN1 constants for this group
    double mean = g_s1[bg] * (1.0 / (64.0 * 4096.0));
    double var  = g_ss1[bg] * (1.0 / (64.0 * 4096.0)) - mean * mean;
    float rs = (float)rsqrt(var + 1e-5);
    float mn = (float)mean;

    // counts for this thread's 4 n
    float w[4];
#pragma unroll
    for (int j = 0; j < 4; j++) w[j] = (float)g_cnt[b*NPTS + n0 + tx*4 + j];

    float lsum = 0.f, lss = 0.f;
#pragma unroll
    for (int i = 0; i < 4; i++) {
        int m = m0 + ty*4 + i;
        float bb = b1[m];
        float ga = g1[m] * rs;
        float bofs = be1[m] - (mn - bb) * ga;   // (v+bb-mn)*ga + be1
        float wdm = wd[m];
#pragma unroll
        for (int j = 0; j < 4; j++) {
            float f = gelu_f(fmaf(acc[i][j], ga, bofs));
            sT[tx*4 + j][ty*4 + i] = f;
            float v2 = f * wdm;
            lsum = fmaf(w[j], v2, lsum);
            lss  = fmaf(w[j], v2*v2, lss);
        }
    }
    __syncthreads();

    // write feats fp16: row n, 64 m = 32 half2; 4 threads per row, 8 half2 each
    {
        int nl = tid >> 2, seg = tid & 3;
        const float* src = &sT[nl][seg * 16];
        __half2 hv[8];
#pragma unroll
        for (int p = 0; p < 8; p++)
            hv[p] = __floats2half2_rn(src[2*p], src[2*p + 1]);
        __half2* dst = g_featsh + (size_t)(b*NPTS + n0 + nl)*(MM/2) + (m0 >> 1) + seg*8;
        *(uint4*)(dst)     = *(uint4*)(hv);
        *(uint4*)(dst + 4) = *(uint4*)(hv + 4);
    }

    red1[tid] = lsum; red2[tid] = lss;
    __syncthreads();
    for (int s = 128; s > 0; s >>= 1) {
        if (tid < s) { red1[tid] += red1[tid + s]; red2[tid] += red2[tid + s]; }
        __syncthreads();
    }
    if (tid == 0) {
        atomicAdd(&g_s2[bg],  (double)red1[0]);
        atomicAdd(&g_ss2[bg], (double)red2[0]);
    }
}

// -------- K4: fused gather(max/min) + GN2 + maxpool + GELU + GEMM2 + GN3 stats --------
// grid (N/32, B), block 256. dyn smem: sI[32][32] int + sH[32][257] f + sW2[64][257] f
#define GG2_SMEM (32*32*4 + 32*257*4 + 64*257*4)
__global__ void k_gg2(const float* __restrict__ wd, const float* __restrict__ gd,
                      const float* __restrict__ bed, const float* __restrict__ w2,
                      const float* __restrict__ b2) {
    extern __shared__ char smraw[];
    int*   sI  = (int*)smraw;                       // [32][32]
    float* sH  = (float*)(smraw + 32*32*4);         // [32][257]
    float* sW2 = (float*)(smraw + 32*32*4 + 32*257*4); // [64][257]
    __shared__ float sacc[4], sss[4];

    int b = blockIdx.y, n0 = blockIdx.x * 32;
    int tid = threadIdx.x;
    if (tid < 4) { sacc[tid] = 0.f; sss[tid] = 0.f; }

    for (int e = tid; e < 32*32; e += 256)
        sI[e] = g_idx[(b*NPTS + n0 + (e >> 5))*NS + (e & 31)];
    for (int e = tid; e < 64*256; e += 256)
        sW2[(e >> 8)*257 + (e & 255)] = w2[e];
    __syncthreads();

    // gather phase: thread = (m-pair, n-half)
    {
        int mp = tid & 127, nh = tid >> 7;
        int m0c = mp * 2;
        // GN2 constants for both channels
        float A[2], Bc[2];
#pragma unroll
        for (int u = 0; u < 2; u++) {
            int m = m0c + u;
            int bg = b*4 + (m >> 6);
            double mean = g_s2[bg] * (1.0 / 8388608.0);
            double var  = g_ss2[bg] * (1.0 / 8388608.0) - mean * mean;
            float rs = (float)rsqrt(var + 1e-5);
            A[u]  = wd[m] * rs * gd[m];
            Bc[u] = bed[m] - (float)((double)rs * mean) * gd[m];
        }
        const __half2* fb = g_featsh + (size_t)b*NPTS*(MM/2) + mp;
        for (int nn = 0; nn < 16; nn++) {
            int n = nh*16 + nn;
            const int* il = sI + n*32;
            __half2 vmax = __half2half2(__float2half(-65504.f));
            __half2 vmin = __half2half2(__float2half( 65504.f));
#pragma unroll
            for (int s = 0; s < NS; s++) {
                __half2 v = fb[(size_t)il[s] * (MM/2)];
                vmax = __hmax2(vmax, v);
                vmin = __hmin2(vmin, v);
            }
            float2 fmax2 = __half22float2(vmax);
            float2 fmin2 = __half22float2(vmin);
            float v0 = (A[0] >= 0.f) ? fmax2.x : fmin2.x;
            float v1 = (A[1] >= 0.f) ? fmax2.y : fmin2.y;
            sH[n*257 + m0c]     = gelu_f(fmaf(A[0], v0, Bc[0]));
            sH[n*257 + m0c + 1] = gelu_f(fmaf(A[1], v1, Bc[1]));
        }
    }
    __syncthreads();

    // GEMM phase: 64c x 32n tile, thread = 2c x 4n
    int tx = tid & 7, ty = tid >> 3;
    float acc[2][4] = {};
#pragma unroll 8
    for (int k = 0; k < 256; k++) {
        float a[2], h[4];
#pragma unroll
        for (int i = 0; i < 2; i++) a[i] = sW2[(ty*2 + i)*257 + k];
#pragma unroll
        for (int j = 0; j < 4; j++) h[j] = sH[(tx*4 + j)*257 + k];
#pragma unroll
        for (int i = 0; i < 2; i++)
#pragma unroll
            for (int j = 0; j < 4; j++)
                acc[i][j] = fmaf(a[i], h[j], acc[i][j]);
    }

    float lsum = 0.f, lss = 0.f;
#pragma unroll
    for (int i = 0; i < 2; i++) {
        int c = ty*2 + i;
        float bb = b2[c];
        float v0 = acc[i][0] + bb, v1 = acc[i][1] + bb;
        float v2 = acc[i][2] + bb, v3 = acc[i][3] + bb;
        float4 o; o.x = v0; o.y = v1; o.z = v2; o.w = v3;
        *(float4*)&g_oraw[(b*CC + c)*NPTS + n0 + tx*4] = o;
        lsum += v0 + v1 + v2 + v3;
        lss  += v0*v0 + v1*v1 + v2*v2 + v3*v3;
    }
    int g = ty >> 3;    // c group = c/16 = (ty*2)/16
    atomicAdd(&sacc[g], lsum);
    atomicAdd(&sss[g],  lss);
    __syncthreads();
    if (tid < 4) {
        atomicAdd(&g_s3[b*4 + tid],  (double)sacc[tid]);
        atomicAdd(&g_ss3[b*4 + tid], (double)sss[tid]);
    }
}

// -------- K5: GN3 + residual --------
__global__ void k_final(const float* __restrict__ x, const float* __restrict__ g2,
                        const float* __restrict__ be2, float* __restrict__ out) {
    int i = blockIdx.x * 256 + threadIdx.x;
    if (i >= BB*CC*NPTS) return;
    int b = i >> 18;
    int c = (i >> 12) & 63;
    int bg = b*4 + (c >> 4);
    double mean = g_s3[bg] * (1.0 / 65536.0);
    double var  = g_ss3[bg] * (1.0 / 65536.0) - mean * mean;
    float rs = (float)rsqrt(var + 1e-5);
    out[i] = (g_oraw[i] - (float)mean) * rs * g2[c] + be2[c] + x[i];
}

extern "C" void kernel_launch(void* const* d_in, const int* in_sizes, int n_in,
                              void* d_out, int out_size) {
    const float* x   = (const float*)d_in[0];
    const float* pos = (const float*)d_in[1];
    const float* w1  = (const float*)d_in[2];
    const float* b1  = (const float*)d_in[3];
    const float* g1  = (const float*)d_in[4];
    const float* be1 = (const float*)d_in[5];
    const float* wd  = (const float*)d_in[6];
    const float* gd  = (const float*)d_in[7];
    const float* bed = (const float*)d_in[8];
    const float* w2  = (const float*)d_in[9];
    const float* b2  = (const float*)d_in[10];
    const float* g2  = (const float*)d_in[11];
    const float* be2 = (const float*)d_in[12];
    float* out = (float*)d_out;

    static int inited = 0;
    if (!inited) {
        cudaFuncSetAttribute(k_ball, cudaFuncAttributeMaxDynamicSharedMemorySize, 3*NPTS*4 + 16*NS*4);
        cudaFuncSetAttribute(k_gram, cudaFuncAttributeMaxDynamicSharedMemorySize, 64*257*4);
        cudaFuncSetAttribute(k_gg2,  cudaFuncAttributeMaxDynamicSharedMemorySize, GG2_SMEM);
        inited = 1;
    }

    k_zero  <<<32, 256>>>();
    k_ball  <<<BB*NPTS/16, 512, 3*NPTS*4 + 16*NS*4>>>(pos);
    k_gram  <<<dim3(16, BB), 256, 64*257*4>>>(x);
    k_stats1<<<64, 256>>>(w1, b1);
    k_gemm1f<<<dim3(NPTS/64, MM/64, BB), 256>>>(x, w1, b1, g1, be1, wd);
    k_gg2   <<<dim3(NPTS/32, BB), 256, GG2_SMEM>>>(wd, gd, bed, w2, b2);
    k_final <<<(BB*CC*NPTS)/256, 256>>>(x, g2, be2, out);
}

// round 3
// speedup vs baseline: 1.0578x; 1.0578x over previous
#include <cuda_runtime.h>
#include <cuda_fp16.h>
#include <math.h>

#define BB 2
#define CC 64
#define NPTS 4096
#define MM 256
#define NS 32
#define R2 0.04f

// -------- scratch (device globals; no allocation allowed) --------
__device__ int     g_idx[BB*NPTS*NS];
__device__ int     g_cnt[BB*NPTS];
__device__ __half2 g_featsh[BB*NPTS*(MM/2)];  // (B, N, M/2) fp16 pairs
__device__ float   g_oraw[BB*CC*NPTS];        // (B, C, N)
__device__ float   g_G[BB*CC*CC];             // per-batch Gram of x
__device__ float   g_sv[BB*CC];               // per-batch row sums of x
__device__ double  g_stat[48];                // s1[8],ss1[8],s2[8],ss2[8],s3[8],ss3[8]

#define G_S1  (g_stat)
#define G_SS1 (g_stat + 8)
#define G_S2  (g_stat + 16)
#define G_SS2 (g_stat + 24)
#define G_S3  (g_stat + 32)
#define G_SS3 (g_stat + 40)

__device__ __forceinline__ float gelu_f(float v) {
    return 0.5f * v * (1.0f + erff(v * 0.70710678118654752f));
}

// -------- K1: ball query (one warp per query point) + counts --------
// 1024 threads = 32 points per block
__global__ void k_ball(const float* __restrict__ pos) {
    extern __shared__ float sm[];
    float* sx = sm;
    float* sy = sm + NPTS;
    float* sz = sm + 2*NPTS;
    int*   widx = (int*)(sm + 3*NPTS);   // 32 warps * 32 entries

    int tid = threadIdx.x;
    int b = blockIdx.x / (NPTS/32);
    int nbase = (blockIdx.x % (NPTS/32)) * 32;
    const float* pb = pos + b * 3 * NPTS;
    for (int i = tid; i < NPTS; i += 1024) {
        sx[i] = pb[i];
        sy[i] = pb[NPTS + i];
        sz[i] = pb[2*NPTS + i];
    }
    __syncthreads();

    int warp = tid >> 5, lane = tid & 31;
    int n = nbase + warp;
    float xn = sx[n], yn = sy[n], zn = sz[n];
    float sqn = xn*xn + yn*yn + zn*zn;
    int cnt = 0, firstm = -1;
    int* wl = widx + warp * NS;

    for (int base = 0; base < NPTS && cnt < NS; base += 32) {
        int mq = base + lane;
        float xm = sx[mq], ym = sy[mq], zm = sz[mq];
        float sqm = xm*xm + ym*ym + zm*zm;
        float dot = xn*xm + yn*ym + zn*zm;
        float d = sqn + sqm - 2.0f * dot;
        bool q = !(d > R2);
        unsigned mask = __ballot_sync(0xffffffffu, q);
        if (mask) {
            if (firstm < 0) firstm = base + __ffs(mask) - 1;
            int nq = __popc(mask);
            int slots = NS - cnt;
            if (q) {
                int rank = __popc(mask & ((1u << lane) - 1u));
                if (rank < slots) wl[cnt + rank] = mq;
            }
            cnt += (nq < slots) ? nq : slots;
        }
    }
    __syncwarp();
    if (lane >= cnt) wl[lane] = firstm;   // pad with first qualifying index
    __syncwarp();
    int j = wl[lane];
    g_idx[(b*NPTS + n)*NS + lane] = j;
    atomicAdd(&g_cnt[b*NPTS + j], 1);
}

// -------- K2a: Gram matrix G = x x^T + row sums, register-tiled --------
// grid (64 n-chunks, B), block 256, 4x4 micro-tile over 64x64 symmetric output
__global__ void k_gram(const float* __restrict__ x) {
    __shared__ float sx[64][65];          // [c][n_local]
    int b = blockIdx.y, n0 = blockIdx.x * 64;
    int tid = threadIdx.x;
    for (int e = tid; e < 4096; e += 256) {
        int c = e >> 6, nn = e & 63;
        sx[c][nn] = x[(b*CC + c)*NPTS + n0 + nn];
    }
    __syncthreads();

    int tx = tid & 15, ty = tid >> 4;
    float acc[4][4] = {};
#pragma unroll 16
    for (int k = 0; k < 64; k++) {
        float a[4], h[4];
#pragma unroll
        for (int i = 0; i < 4; i++) a[i] = sx[ty*4 + i][k];
#pragma unroll
        for (int j = 0; j < 4; j++) h[j] = sx[tx*4 + j][k];
#pragma unroll
        for (int i = 0; i < 4; i++)
#pragma unroll
            for (int j = 0; j < 4; j++)
                acc[i][j] = fmaf(a[i], h[j], acc[i][j]);
    }
    float* Gb = g_G + b*CC*CC;
#pragma unroll
    for (int i = 0; i < 4; i++)
#pragma unroll
        for (int j = 0; j < 4; j++)
            atomicAdd(&Gb[(ty*4 + i)*CC + tx*4 + j], acc[i][j]);

    if (tid < CC) {
        float s = 0.f;
#pragma unroll
        for (int nn = 0; nn < 64; nn++) s += sx[tid][nn];
        atomicAdd(&g_sv[b*CC + tid], s);
    }
}

// -------- K2b: GN1 group stats from Gram, one block per (b,group) --------
// grid 8, block 512; thread = (m in 0..63, part in 0..7)
__global__ void k_stats1(const float* __restrict__ w1, const float* __restrict__ b1) {
    __shared__ float sG[CC*CC];          // 16KB
    __shared__ float sw[64][65];
    __shared__ float ssv[CC];
    __shared__ double sd[64], ssd[64];
    int bg = blockIdx.x;
    int b = bg >> 2, m0 = (bg & 3) * 64;
    int tid = threadIdx.x;
    for (int e = tid; e < CC*CC; e += 512) sG[e] = g_G[b*CC*CC + e];
    for (int e = tid; e < 64*CC; e += 512) sw[e >> 6][e & 63] = w1[(m0 + (e >> 6))*CC + (e & 63)];
    if (tid < CC) ssv[tid] = g_sv[b*CC + tid];
    __syncthreads();

    int mi = tid >> 3, part = tid & 7;
    float q = 0.f, l = 0.f;
#pragma unroll
    for (int cc = 0; cc < 8; cc++) {
        int c = part*8 + cc;
        float wc = sw[mi][c];
        float in0 = 0.f, in1 = 0.f;
#pragma unroll
        for (int c2 = 0; c2 < 64; c2 += 2) {
            in0 = fmaf(sw[mi][c2],   sG[c*CC + c2],   in0);
            in1 = fmaf(sw[mi][c2+1], sG[c*CC + c2+1], in1);
        }
        q = fmaf(wc, in0 + in1, q);
        l = fmaf(wc, ssv[c], l);
    }
#pragma unroll
    for (int o = 4; o > 0; o >>= 1) {
        q += __shfl_down_sync(0xffffffffu, q, o);
        l += __shfl_down_sync(0xffffffffu, l, o);
    }
    if (part == 0) {
        double bb = (double)b1[m0 + mi];
        sd[mi]  = (double)l + 4096.0 * bb;
        ssd[mi] = (double)q + 2.0 * bb * (double)l + 4096.0 * bb * bb;
    }
    __syncthreads();
    for (int s = 32; s > 0; s >>= 1) {
        if (tid < s) { sd[tid] += sd[tid + s]; ssd[tid] += ssd[tid + s]; }
        __syncthreads();
    }
    if (tid == 0) { G_S1[bg] = sd[0]; G_SS1[bg] = ssd[0]; }
}

// -------- K3: h = w1@x + b1, GN1 + GELU in epilogue,
//          write feats fp16 transposed, fused count-weighted GN2 stats --------
__global__ void k_gemm1f(const float* __restrict__ x, const float* __restrict__ w1,
                         const float* __restrict__ b1, const float* __restrict__ g1,
                         const float* __restrict__ be1, const float* __restrict__ wd) {
    __shared__ float sW[64][65];
    __shared__ float sX[64][64];
    __shared__ float sT[64][65];
    __shared__ float red1[256], red2[256];
    int b = blockIdx.z, m0 = blockIdx.y * 64, n0 = blockIdx.x * 64;
    int tid = threadIdx.x;
    int bg = b*4 + blockIdx.y;

    for (int e = tid; e < 4096; e += 256) {
        int mr = e >> 6, cr = e & 63;
        sW[mr][cr] = w1[(m0 + mr)*CC + cr];
    }
    for (int e = tid; e < 4096; e += 256) {
        int cr = e >> 6, nr = e & 63;
        sX[cr][nr] = x[(b*CC + cr)*NPTS + n0 + nr];
    }
    __syncthreads();

    int tx = tid & 15, ty = tid >> 4;
    float acc[4][4] = {};
#pragma unroll 16
    for (int k = 0; k < 64; k++) {
        float a[4], h[4];
#pragma unroll
        for (int i = 0; i < 4; i++) a[i] = sW[ty*4 + i][k];
#pragma unroll
        for (int j = 0; j < 4; j++) h[j] = sX[k][tx*4 + j];
#pragma unroll
        for (int i = 0; i < 4; i++)
#pragma unroll
            for (int j = 0; j < 4; j++)
                acc[i][j] = fmaf(a[i], h[j], acc[i][j]);
    }

    double mean = G_S1[bg] * (1.0 / (64.0 * 4096.0));
    double var  = G_SS1[bg] * (1.0 / (64.0 * 4096.0)) - mean * mean;
    float rs = (float)rsqrt(var + 1e-5);
    float mn = (float)mean;

    float w[4];
#pragma unroll
    for (int j = 0; j < 4; j++) w[j] = (float)g_cnt[b*NPTS + n0 + tx*4 + j];

    float lsum = 0.f, lss = 0.f;
#pragma unroll
    for (int i = 0; i < 4; i++) {
        int m = m0 + ty*4 + i;
        float bb = b1[m];
        float ga = g1[m] * rs;
        float bofs = be1[m] - (mn - bb) * ga;
        float wdm = wd[m];
#pragma unroll
        for (int j = 0; j < 4; j++) {
            float f = gelu_f(fmaf(acc[i][j], ga, bofs));
            sT[tx*4 + j][ty*4 + i] = f;
            float v2 = f * wdm;
            lsum = fmaf(w[j], v2, lsum);
            lss  = fmaf(w[j], v2*v2, lss);
        }
    }
    __syncthreads();

    {
        int nl = tid >> 2, seg = tid & 3;
        const float* src = &sT[nl][seg * 16];
        __half2 hv[8];
#pragma unroll
        for (int p = 0; p < 8; p++)
            hv[p] = __floats2half2_rn(src[2*p], src[2*p + 1]);
        __half2* dst = g_featsh + (size_t)(b*NPTS + n0 + nl)*(MM/2) + (m0 >> 1) + seg*8;
        *(uint4*)(dst)     = *(uint4*)(hv);
        *(uint4*)(dst + 4) = *(uint4*)(hv + 4);
    }

    red1[tid] = lsum; red2[tid] = lss;
    __syncthreads();
    for (int s = 128; s > 0; s >>= 1) {
        if (tid < s) { red1[tid] += red1[tid + s]; red2[tid] += red2[tid + s]; }
        __syncthreads();
    }
    if (tid == 0) {
        atomicAdd(&G_S2[bg],  (double)red1[0]);
        atomicAdd(&G_SS2[bg], (double)red2[0]);
    }
}

// -------- K4: fused gather(max/min) + GN2 + maxpool + GELU + GEMM2 + GN3 stats --------
#define GG2_SMEM (32*32*4 + 32*257*4 + 64*257*4)
__global__ void k_gg2(const float* __restrict__ wd, const float* __restrict__ gd,
                      const float* __restrict__ bed, const float* __restrict__ w2,
                      const float* __restrict__ b2) {
    extern __shared__ char smraw[];
    int*   sI  = (int*)smraw;                          // [32][32]
    float* sH  = (float*)(smraw + 32*32*4);            // [32][257]
    float* sW2 = (float*)(smraw + 32*32*4 + 32*257*4); // [64][257]
    __shared__ float sacc[4], sss[4];

    int b = blockIdx.y, n0 = blockIdx.x * 32;
    int tid = threadIdx.x;
    if (tid < 4) { sacc[tid] = 0.f; sss[tid] = 0.f; }

    for (int e = tid; e < 32*32; e += 256)
        sI[e] = g_idx[(b*NPTS + n0 + (e >> 5))*NS + (e & 31)];
    for (int e = tid; e < 64*256; e += 256)
        sW2[(e >> 8)*257 + (e & 255)] = w2[e];
    __syncthreads();

    {
        int mp = tid & 127, nh = tid >> 7;
        int m0c = mp * 2;
        float A[2], Bc[2];
#pragma unroll
        for (int u = 0; u < 2; u++) {
            int m = m0c + u;
            int bg = b*4 + (m >> 6);
            double mean = G_S2[bg] * (1.0 / 8388608.0);
            double var  = G_SS2[bg] * (1.0 / 8388608.0) - mean * mean;
            float rs = (float)rsqrt(var + 1e-5);
            A[u]  = wd[m] * rs * gd[m];
            Bc[u] = bed[m] - (float)((double)rs * mean) * gd[m];
        }
        const __half2* fb = g_featsh + (size_t)b*NPTS*(MM/2) + mp;
        for (int nn = 0; nn < 16; nn++) {
            int n = nh*16 + nn;
            const int* il = sI + n*32;
            __half2 neg = __half2half2(__float2half(-65504.f));
            __half2 pos = __half2half2(__float2half( 65504.f));
            __half2 vmax0 = neg, vmax1 = neg, vmin0 = pos, vmin1 = pos;
#pragma unroll
            for (int s = 0; s < NS; s += 2) {
                __half2 v0 = fb[(size_t)il[s]   * (MM/2)];
                __half2 v1 = fb[(size_t)il[s+1] * (MM/2)];
                vmax0 = __hmax2(vmax0, v0); vmin0 = __hmin2(vmin0, v0);
                vmax1 = __hmax2(vmax1, v1); vmin1 = __hmin2(vmin1, v1);
            }
            __half2 vmax = __hmax2(vmax0, vmax1);
            __half2 vmin = __hmin2(vmin0, vmin1);
            float2 fmax2 = __half22float2(vmax);
            float2 fmin2 = __half22float2(vmin);
            float v0 = (A[0] >= 0.f) ? fmax2.x : fmin2.x;
            float v1 = (A[1] >= 0.f) ? fmax2.y : fmin2.y;
            sH[n*257 + m0c]     = gelu_f(fmaf(A[0], v0, Bc[0]));
            sH[n*257 + m0c + 1] = gelu_f(fmaf(A[1], v1, Bc[1]));
        }
    }
    __syncthreads();

    int tx = tid & 7, ty = tid >> 3;
    float acc[2][4] = {};
#pragma unroll 8
    for (int k = 0; k < 256; k++) {
        float a[2], h[4];
#pragma unroll
        for (int i = 0; i < 2; i++) a[i] = sW2[(ty*2 + i)*257 + k];
#pragma unroll
        for (int j = 0; j < 4; j++) h[j] = sH[(tx*4 + j)*257 + k];
#pragma unroll
        for (int i = 0; i < 2; i++)
#pragma unroll
            for (int j = 0; j < 4; j++)
                acc[i][j] = fmaf(a[i], h[j], acc[i][j]);
    }

    float lsum = 0.f, lss = 0.f;
#pragma unroll
    for (int i = 0; i < 2; i++) {
        int c = ty*2 + i;
        float bb = b2[c];
        float v0 = acc[i][0] + bb, v1 = acc[i][1] + bb;
        float v2 = acc[i][2] + bb, v3 = acc[i][3] + bb;
        float4 o; o.x = v0; o.y = v1; o.z = v2; o.w = v3;
        *(float4*)&g_oraw[(b*CC + c)*NPTS + n0 + tx*4] = o;
        lsum += v0 + v1 + v2 + v3;
        lss  += v0*v0 + v1*v1 + v2*v2 + v3*v3;
    }
    int g = ty >> 3;
    atomicAdd(&sacc[g], lsum);
    atomicAdd(&sss[g],  lss);
    __syncthreads();
    if (tid < 4) {
        atomicAdd(&G_S3[b*4 + tid],  (double)sacc[tid]);
        atomicAdd(&G_SS3[b*4 + tid], (double)sss[tid]);
    }
}

// -------- K5: GN3 + residual --------
__global__ void k_final(const float* __restrict__ x, const float* __restrict__ g2,
                        const float* __restrict__ be2, float* __restrict__ out) {
    int i4 = blockIdx.x * 256 + threadIdx.x;
    if (i4 >= BB*CC*NPTS/4) return;
    int i = i4 * 4;
    int b = i >> 18;
    int c = (i >> 12) & 63;
    int bg = b*4 + (c >> 4);
    double mean = G_S3[bg] * (1.0 / 65536.0);
    double var  = G_SS3[bg] * (1.0 / 65536.0) - mean * mean;
    float rs = (float)rsqrt(var + 1e-5);
    float ga = rs * g2[c];
    float bo = be2[c] - (float)mean * ga;
    float4 o = *(const float4*)&g_oraw[i];
    float4 xi = *(const float4*)&x[i];
    o.x = fmaf(o.x, ga, bo) + xi.x;
    o.y = fmaf(o.y, ga, bo) + xi.y;
    o.z = fmaf(o.z, ga, bo) + xi.z;
    o.w = fmaf(o.w, ga, bo) + xi.w;
    *(float4*)&out[i] = o;
}

extern "C" void kernel_launch(void* const* d_in, const int* in_sizes, int n_in,
                              void* d_out, int out_size) {
    const float* x   = (const float*)d_in[0];
    const float* pos = (const float*)d_in[1];
    const float* w1  = (const float*)d_in[2];
    const float* b1  = (const float*)d_in[3];
    const float* g1  = (const float*)d_in[4];
    const float* be1 = (const float*)d_in[5];
    const float* wd  = (const float*)d_in[6];
    const float* gd  = (const float*)d_in[7];
    const float* bed = (const float*)d_in[8];
    const float* w2  = (const float*)d_in[9];
    const float* b2  = (const float*)d_in[10];
    const float* g2  = (const float*)d_in[11];
    const float* be2 = (const float*)d_in[12];
    float* out = (float*)d_out;

    static int inited = 0;
    if (!inited) {
        cudaFuncSetAttribute(k_ball, cudaFuncAttributeMaxDynamicSharedMemorySize, 3*NPTS*4 + 32*NS*4);
        cudaFuncSetAttribute(k_gg2,  cudaFuncAttributeMaxDynamicSharedMemorySize, GG2_SMEM);
        inited = 1;
    }

    void *p_cnt, *p_stat, *p_G, *p_sv;
    cudaGetSymbolAddress(&p_cnt,  g_cnt);
    cudaGetSymbolAddress(&p_stat, g_stat);
    cudaGetSymbolAddress(&p_G,    g_G);
    cudaGetSymbolAddress(&p_sv,   g_sv);

    cudaMemsetAsync(p_cnt,  0, BB*NPTS*sizeof(int));
    cudaMemsetAsync(p_stat, 0, 48*sizeof(double));
    cudaMemsetAsync(p_G,    0, BB*CC*CC*sizeof(float));
    cudaMemsetAsync(p_sv,   0, BB*CC*sizeof(float));

    k_ball  <<<BB*NPTS/32, 1024, 3*NPTS*4 + 32*NS*4>>>(pos);
    k_gram  <<<dim3(64, BB), 256>>>(x);
    k_stats1<<<8, 512>>>(w1, b1);
    k_gemm1f<<<dim3(NPTS/64, MM/64, BB), 256>>>(x, w1, b1, g1, be1, wd);
    k_gg2   <<<dim3(NPTS/32, BB), 256, GG2_SMEM>>>(wd, gd, bed, w2, b2);
    k_final <<<(BB*CC*NPTS/4 + 255)/256, 256>>>(x, g2, be2, out);
}

// round 4
// speedup vs baseline: 1.0732x; 1.0145x over previous
#include <cuda_runtime.h>
#include <cuda_fp16.h>
#include <math.h>

#define BB 2
#define CC 64
#define NPTS 4096
#define MM 256
#define NS 32
#define R2 0.04f

// -------- scratch (device globals; no allocation allowed) --------
__device__ int     g_idx[BB*NPTS*NS];
__device__ int     g_cnt[BB*NPTS];
__device__ __half2 g_featsh[BB*NPTS*(MM/2)];  // (B, N, M/2) fp16 pairs
__device__ float   g_oraw[BB*CC*NPTS];        // (B, C, N)
__device__ float   g_G[BB*CC*CC];             // per-batch Gram of x
__device__ float   g_sv[BB*CC];               // per-batch row sums of x
__device__ double  g_stat[48];                // s1[8],ss1[8],s2[8],ss2[8],s3[8],ss3[8]

#define G_S1  (g_stat)
#define G_SS1 (g_stat + 8)
#define G_S2  (g_stat + 16)
#define G_SS2 (g_stat + 24)
#define G_S3  (g_stat + 32)
#define G_SS3 (g_stat + 40)

__device__ __forceinline__ float gelu_f(float v) {
    return 0.5f * v * (1.0f + erff(v * 0.70710678118654752f));
}

// -------- K1: ball query (one warp per query point) + counts --------
__global__ void k_ball(const float* __restrict__ pos) {
    extern __shared__ float sm[];
    float* sx = sm;
    float* sy = sm + NPTS;
    float* sz = sm + 2*NPTS;
    int*   widx = (int*)(sm + 3*NPTS);   // 32 warps * 32 entries

    int tid = threadIdx.x;
    int b = blockIdx.x / (NPTS/32);
    int nbase = (blockIdx.x % (NPTS/32)) * 32;
    const float* pb = pos + b * 3 * NPTS;
    for (int i = tid; i < NPTS; i += 1024) {
        sx[i] = pb[i];
        sy[i] = pb[NPTS + i];
        sz[i] = pb[2*NPTS + i];
    }
    __syncthreads();

    int warp = tid >> 5, lane = tid & 31;
    int n = nbase + warp;
    float xn = sx[n], yn = sy[n], zn = sz[n];
    float sqn = xn*xn + yn*yn + zn*zn;
    int cnt = 0, firstm = -1;
    int* wl = widx + warp * NS;

    for (int base = 0; base < NPTS && cnt < NS; base += 32) {
        int mq = base + lane;
        float xm = sx[mq], ym = sy[mq], zm = sz[mq];
        float sqm = xm*xm + ym*ym + zm*zm;
        float dot = xn*xm + yn*ym + zn*zm;
        float d = sqn + sqm - 2.0f * dot;
        bool q = !(d > R2);
        unsigned mask = __ballot_sync(0xffffffffu, q);
        if (mask) {
            if (firstm < 0) firstm = base + __ffs(mask) - 1;
            int nq = __popc(mask);
            int slots = NS - cnt;
            if (q) {
                int rank = __popc(mask & ((1u << lane) - 1u));
                if (rank < slots) wl[cnt + rank] = mq;
            }
            cnt += (nq < slots) ? nq : slots;
        }
    }
    __syncwarp();
    if (lane >= cnt) wl[lane] = firstm;
    __syncwarp();
    int j = wl[lane];
    g_idx[(b*NPTS + n)*NS + lane] = j;
    atomicAdd(&g_cnt[b*NPTS + j], 1);
}

// -------- K2a: Gram matrix G = x x^T + row sums --------
__global__ void k_gram(const float* __restrict__ x) {
    __shared__ float sx[64][65];
    int b = blockIdx.y, n0 = blockIdx.x * 64;
    int tid = threadIdx.x;
    for (int e = tid; e < 4096; e += 256) {
        int c = e >> 6, nn = e & 63;
        sx[c][nn] = x[(b*CC + c)*NPTS + n0 + nn];
    }
    __syncthreads();

    int tx = tid & 15, ty = tid >> 4;
    float acc[4][4] = {};
#pragma unroll 16
    for (int k = 0; k < 64; k++) {
        float a[4], h[4];
#pragma unroll
        for (int i = 0; i < 4; i++) a[i] = sx[ty*4 + i][k];
#pragma unroll
        for (int j = 0; j < 4; j++) h[j] = sx[tx*4 + j][k];
#pragma unroll
        for (int i = 0; i < 4; i++)
#pragma unroll
            for (int j = 0; j < 4; j++)
                acc[i][j] = fmaf(a[i], h[j], acc[i][j]);
    }
    float* Gb = g_G + b*CC*CC;
#pragma unroll
    for (int i = 0; i < 4; i++)
#pragma unroll
        for (int j = 0; j < 4; j++)
            atomicAdd(&Gb[(ty*4 + i)*CC + tx*4 + j], acc[i][j]);

    if (tid < CC) {
        float s = 0.f;
#pragma unroll
        for (int nn = 0; nn < 64; nn++) s += sx[tid][nn];
        atomicAdd(&g_sv[b*CC + tid], s);
    }
}

// -------- K2b: GN1 group stats from Gram --------
__global__ void k_stats1(const float* __restrict__ w1, const float* __restrict__ b1) {
    __shared__ float sG[CC*CC];
    __shared__ float sw[64][65];
    __shared__ float ssv[CC];
    __shared__ double sd[64], ssd[64];
    int bg = blockIdx.x;
    int b = bg >> 2, m0 = (bg & 3) * 64;
    int tid = threadIdx.x;
    for (int e = tid; e < CC*CC; e += 512) sG[e] = g_G[b*CC*CC + e];
    for (int e = tid; e < 64*CC; e += 512) sw[e >> 6][e & 63] = w1[(m0 + (e >> 6))*CC + (e & 63)];
    if (tid < CC) ssv[tid] = g_sv[b*CC + tid];
    __syncthreads();

    int mi = tid >> 3, part = tid & 7;
    float q = 0.f, l = 0.f;
#pragma unroll
    for (int cc = 0; cc < 8; cc++) {
        int c = part*8 + cc;
        float wc = sw[mi][c];
        float in0 = 0.f, in1 = 0.f;
#pragma unroll
        for (int c2 = 0; c2 < 64; c2 += 2) {
            in0 = fmaf(sw[mi][c2],   sG[c*CC + c2],   in0);
            in1 = fmaf(sw[mi][c2+1], sG[c*CC + c2+1], in1);
        }
        q = fmaf(wc, in0 + in1, q);
        l = fmaf(wc, ssv[c], l);
    }
#pragma unroll
    for (int o = 4; o > 0; o >>= 1) {
        q += __shfl_down_sync(0xffffffffu, q, o);
        l += __shfl_down_sync(0xffffffffu, l, o);
    }
    if (part == 0) {
        double bb = (double)b1[m0 + mi];
        sd[mi]  = (double)l + 4096.0 * bb;
        ssd[mi] = (double)q + 2.0 * bb * (double)l + 4096.0 * bb * bb;
    }
    __syncthreads();
    for (int s = 32; s > 0; s >>= 1) {
        if (tid < s) { sd[tid] += sd[tid + s]; ssd[tid] += ssd[tid + s]; }
        __syncthreads();
    }
    if (tid == 0) { G_S1[bg] = sd[0]; G_SS1[bg] = ssd[0]; }
}

// -------- K3: GEMM1 (64m x 128n tile, 8m x 4n thread) + GN1 + GELU
//          + direct fp16 feats write + count-weighted GN2 stats --------
// dyn smem: sWt[64k][68] + sX[64k][128]
#define G1_SMEM ((64*68 + 64*128)*4)
__global__ void k_gemm1f(const float* __restrict__ x, const float* __restrict__ w1,
                         const float* __restrict__ b1, const float* __restrict__ g1,
                         const float* __restrict__ be1, const float* __restrict__ wd) {
    extern __shared__ float smf[];
    float* sWt = smf;             // [k][m] pitch 68
    float* sX  = smf + 64*68;     // [k][n] pitch 128
    __shared__ float red1[256], red2[256];
    int b = blockIdx.z, m0 = blockIdx.y * 64, n0 = blockIdx.x * 128;
    int tid = threadIdx.x;
    int bg = b*4 + blockIdx.y;

    for (int e = tid; e < 64*64; e += 256) {
        int m = e >> 6, c = e & 63;
        sWt[c*68 + m] = w1[(m0 + m)*CC + c];
    }
    for (int e = tid; e < 64*128; e += 256) {
        int c = e >> 7, nn = e & 127;
        sX[c*128 + nn] = x[(b*CC + c)*NPTS + n0 + nn];
    }
    __syncthreads();

    int tx = tid & 31, ty = tid >> 5;    // n-lane (4n), m-octet (8m)
    float acc[8][4] = {};
#pragma unroll 8
    for (int k = 0; k < 64; k++) {
        float4 a0 = *(float4*)&sWt[k*68 + ty*8];
        float4 a1 = *(float4*)&sWt[k*68 + ty*8 + 4];
        float4 h  = *(float4*)&sX[k*128 + tx*4];
        float a[8] = {a0.x, a0.y, a0.z, a0.w, a1.x, a1.y, a1.z, a1.w};
        float hh[4] = {h.x, h.y, h.z, h.w};
#pragma unroll
        for (int i = 0; i < 8; i++)
#pragma unroll
            for (int j = 0; j < 4; j++)
                acc[i][j] = fmaf(a[i], hh[j], acc[i][j]);
    }

    double mean = G_S1[bg] * (1.0 / (64.0 * 4096.0));
    double var  = G_SS1[bg] * (1.0 / (64.0 * 4096.0)) - mean * mean;
    float rs = (float)rsqrt(var + 1e-5);
    float mn = (float)mean;

    float w[4];
#pragma unroll
    for (int j = 0; j < 4; j++) w[j] = (float)g_cnt[b*NPTS + n0 + tx*4 + j];

    float f[8][4];
    float lsum = 0.f, lss = 0.f;
#pragma unroll
    for (int i = 0; i < 8; i++) {
        int m = m0 + ty*8 + i;
        float bb = b1[m];
        float ga = g1[m] * rs;
        float bofs = be1[m] - (mn - bb) * ga;
        float wdm = wd[m];
#pragma unroll
        for (int j = 0; j < 4; j++) {
            float v = gelu_f(fmaf(acc[i][j], ga, bofs));
            f[i][j] = v;
            float v2 = v * wdm;
            lsum = fmaf(w[j], v2, lsum);
            lss  = fmaf(w[j], v2*v2, lss);
        }
    }

    // direct fp16 write: per n, 8 consecutive m = 4 half2 = one uint4
#pragma unroll
    for (int j = 0; j < 4; j++) {
        __half2 hv[4];
#pragma unroll
        for (int p = 0; p < 4; p++)
            hv[p] = __floats2half2_rn(f[2*p][j], f[2*p+1][j]);
        int n = n0 + tx*4 + j;
        __half2* dst = g_featsh + (size_t)(b*NPTS + n)*(MM/2) + (m0 >> 1) + ty*4;
        *(uint4*)dst = *(uint4*)hv;
    }

    red1[tid] = lsum; red2[tid] = lss;
    __syncthreads();
    for (int s = 128; s > 0; s >>= 1) {
        if (tid < s) { red1[tid] += red1[tid + s]; red2[tid] += red2[tid + s]; }
        __syncthreads();
    }
    if (tid == 0) {
        atomicAdd(&G_S2[bg],  (double)red1[0]);
        atomicAdd(&G_SS2[bg], (double)red2[0]);
    }
}

// -------- K4: fused gather + GN2 + maxpool + GELU + GEMM2 + GN3 stats --------
// dyn smem: sI[32][32] int + sH[256k][33] f + sW2t[256k][68] f
#define GG2_SMEM (32*32*4 + 256*33*4 + 256*68*4)
__global__ void k_gg2(const float* __restrict__ wd, const float* __restrict__ gd,
                      const float* __restrict__ bed, const float* __restrict__ w2,
                      const float* __restrict__ b2) {
    extern __shared__ char smraw[];
    int*   sI   = (int*)smraw;                           // [32n][32s]
    float* sH   = (float*)(smraw + 32*32*4);             // [m][n] pitch 33
    float* sW2t = (float*)(smraw + 32*32*4 + 256*33*4);  // [k][c] pitch 68
    __shared__ float sacc[4], sss[4];

    int b = blockIdx.y, n0 = blockIdx.x * 32;
    int tid = threadIdx.x;
    if (tid < 4) { sacc[tid] = 0.f; sss[tid] = 0.f; }

    for (int e = tid; e < 32*32; e += 256)
        sI[e] = g_idx[(b*NPTS + n0 + (e >> 5))*NS + (e & 31)];
    for (int e = tid; e < 64*256; e += 256) {
        int c = e >> 8, k = e & 255;
        sW2t[k*68 + c] = w2[e];
    }
    __syncthreads();

    // gather phase: thread = (m-pair mp, n-half nh)
    {
        int mp = tid & 127, nh = tid >> 7;
        int m0c = mp * 2;
        float A[2], Bc[2];
#pragma unroll
        for (int u = 0; u < 2; u++) {
            int m = m0c + u;
            int bg = b*4 + (m >> 6);
            double mean = G_S2[bg] * (1.0 / 8388608.0);
            double var  = G_SS2[bg] * (1.0 / 8388608.0) - mean * mean;
            float rsv = (float)rsqrt(var + 1e-5);
            A[u]  = wd[m] * rsv * gd[m];
            Bc[u] = bed[m] - (float)((double)rsv * mean) * gd[m];
        }
        const __half2* fb = g_featsh + (size_t)b*NPTS*(MM/2) + mp;
        for (int nn = 0; nn < 16; nn++) {
            int n = nh*16 + nn;
            const int* il = sI + n*32;
            __half2 negv = __half2half2(__float2half(-65504.f));
            __half2 posv = __half2half2(__float2half( 65504.f));
            __half2 vmax0 = negv, vmax1 = negv, vmin0 = posv, vmin1 = posv;
#pragma unroll
            for (int s = 0; s < NS; s += 2) {
                __half2 v0 = fb[(size_t)il[s]   * (MM/2)];
                __half2 v1 = fb[(size_t)il[s+1] * (MM/2)];
                vmax0 = __hmax2(vmax0, v0); vmin0 = __hmin2(vmin0, v0);
                vmax1 = __hmax2(vmax1, v1); vmin1 = __hmin2(vmin1, v1);
            }
            __half2 vmax = __hmax2(vmax0, vmax1);
            __half2 vmin = __hmin2(vmin0, vmin1);
            float2 fmax2 = __half22float2(vmax);
            float2 fmin2 = __half22float2(vmin);
            float v0 = (A[0] >= 0.f) ? fmax2.x : fmin2.x;
            float v1 = (A[1] >= 0.f) ? fmax2.y : fmin2.y;
            sH[(m0c)*33 + n]     = gelu_f(fmaf(A[0], v0, Bc[0]));
            sH[(m0c + 1)*33 + n] = gelu_f(fmaf(A[1], v1, Bc[1]));
        }
    }
    __syncthreads();

    // GEMM phase: thread = (n-lane tx, c-octet ty); acc[8]
    int tx = tid & 31, ty = tid >> 5;
    float acc[8] = {};
#pragma unroll 4
    for (int k = 0; k < 256; k++) {
        float4 a0 = *(float4*)&sW2t[k*68 + ty*8];
        float4 a1 = *(float4*)&sW2t[k*68 + ty*8 + 4];
        float hv = sH[k*33 + tx];
        acc[0] = fmaf(a0.x, hv, acc[0]);
        acc[1] = fmaf(a0.y, hv, acc[1]);
        acc[2] = fmaf(a0.z, hv, acc[2]);
        acc[3] = fmaf(a0.w, hv, acc[3]);
        acc[4] = fmaf(a1.x, hv, acc[4]);
        acc[5] = fmaf(a1.y, hv, acc[5]);
        acc[6] = fmaf(a1.z, hv, acc[6]);
        acc[7] = fmaf(a1.w, hv, acc[7]);
    }

    float lsum = 0.f, lss = 0.f;
#pragma unroll
    for (int i = 0; i < 8; i++) {
        int c = ty*8 + i;
        float v = acc[i] + b2[c];
        g_oraw[(b*CC + c)*NPTS + n0 + tx] = v;
        lsum += v;
        lss  += v*v;
    }
    int g = ty >> 1;    // (ty*8)/16
    atomicAdd(&sacc[g], lsum);
    atomicAdd(&sss[g],  lss);
    __syncthreads();
    if (tid < 4) {
        atomicAdd(&G_S3[b*4 + tid],  (double)sacc[tid]);
        atomicAdd(&G_SS3[b*4 + tid], (double)sss[tid]);
    }
}

// -------- K5: GN3 + residual --------
__global__ void k_final(const float* __restrict__ x, const float* __restrict__ g2,
                        const float* __restrict__ be2, float* __restrict__ out) {
    int i4 = blockIdx.x * 256 + threadIdx.x;
    if (i4 >= BB*CC*NPTS/4) return;
    int i = i4 * 4;
    int b = i >> 18;
    int c = (i >> 12) & 63;
    int bg = b*4 + (c >> 4);
    double mean = G_S3[bg] * (1.0 / 65536.0);
    double var  = G_SS3[bg] * (1.0 / 65536.0) - mean * mean;
    float rs = (float)rsqrt(var + 1e-5);
    float ga = rs * g2[c];
    float bo = be2[c] - (float)mean * ga;
    float4 o = *(const float4*)&g_oraw[i];
    float4 xi = *(const float4*)&x[i];
    o.x = fmaf(o.x, ga, bo) + xi.x;
    o.y = fmaf(o.y, ga, bo) + xi.y;
    o.z = fmaf(o.z, ga, bo) + xi.z;
    o.w = fmaf(o.w, ga, bo) + xi.w;
    *(float4*)&out[i] = o;
}

extern "C" void kernel_launch(void* const* d_in, const int* in_sizes, int n_in,
                              void* d_out, int out_size) {
    const float* x   = (const float*)d_in[0];
    const float* pos = (const float*)d_in[1];
    const float* w1  = (const float*)d_in[2];
    const float* b1  = (const float*)d_in[3];
    const float* g1  = (const float*)d_in[4];
    const float* be1 = (const float*)d_in[5];
    const float* wd  = (const float*)d_in[6];
    const float* gd  = (const float*)d_in[7];
    const float* bed = (const float*)d_in[8];
    const float* w2  = (const float*)d_in[9];
    const float* b2  = (const float*)d_in[10];
    const float* g2  = (const float*)d_in[11];
    const float* be2 = (const float*)d_in[12];
    float* out = (float*)d_out;

    static int inited = 0;
    if (!inited) {
        cudaFuncSetAttribute(k_ball,   cudaFuncAttributeMaxDynamicSharedMemorySize, 3*NPTS*4 + 32*NS*4);
        cudaFuncSetAttribute(k_gemm1f, cudaFuncAttributeMaxDynamicSharedMemorySize, G1_SMEM);
        cudaFuncSetAttribute(k_gg2,    cudaFuncAttributeMaxDynamicSharedMemorySize, GG2_SMEM);
        inited = 1;
    }

    void *p_cnt, *p_stat, *p_G, *p_sv;
    cudaGetSymbolAddress(&p_cnt,  g_cnt);
    cudaGetSymbolAddress(&p_stat, g_stat);
    cudaGetSymbolAddress(&p_G,    g_G);
    cudaGetSymbolAddress(&p_sv,   g_sv);

    cudaMemsetAsync(p_cnt,  0, BB*NPTS*sizeof(int));
    cudaMemsetAsync(p_stat, 0, 48*sizeof(double));
    cudaMemsetAsync(p_G,    0, BB*CC*CC*sizeof(float));
    cudaMemsetAsync(p_sv,   0, BB*CC*sizeof(float));

    k_ball  <<<BB*NPTS/32, 1024, 3*NPTS*4 + 32*NS*4>>>(pos);
    k_gram  <<<dim3(64, BB), 256>>>(x);
    k_stats1<<<8, 512>>>(w1, b1);
    k_gemm1f<<<dim3(NPTS/128, MM/64, BB), 256, G1_SMEM>>>(x, w1, b1, g1, be1, wd);
    k_gg2   <<<dim3(NPTS/32, BB), 256, GG2_SMEM>>>(wd, gd, bed, w2, b2);
    k_final <<<(BB*CC*NPTS/4 + 255)/256, 256>>>(x, g2, be2, out);
}